// round 1
// baseline (speedup 1.0000x reference)
#include <cuda_runtime.h>
#include <math.h>
#include <stdint.h>

// Problem constants (fixed shapes for this problem)
#define NN   100000
#define MAXE 1600000
#define HID  128
#define NFT  8

// ---------------- static device scratch (no allocations allowed) ------------
__device__ int   g_deg[NN];
__device__ int   g_off[NN + 1];
__device__ int   g_pos[NN];
__device__ float g_dinv[NN];
__device__ int   g_srcs[MAXE];
__device__ float g_bufA[(size_t)NN * HID];   // yw1 -> yw2
__device__ float g_bufB[(size_t)NN * HID];   // h1  -> h2
__device__ int   g_is64;

// ---------------- dtype detection: int64 vs int32 edge_index ----------------
// int64 little-endian: odd 32-bit words are high halves == 0 (values < 2^17).
// int32: odd words are dst indices, random in [0, 1e5) -> nonzero w.h.p.
__global__ void detect_kernel(const int* __restrict__ ew) {
    __shared__ int s_bad;
    if (threadIdx.x == 0) s_bad = 0;
    __syncthreads();
    int bad = 0;
    for (int i = threadIdx.x; i < 128; i += blockDim.x)
        if (ew[2 * i + 1] != 0) bad = 1;
    if (bad) atomicOr(&s_bad, 1);
    __syncthreads();
    if (threadIdx.x == 0) g_is64 = s_bad ? 0 : 1;
}

__global__ void zero_deg_kernel(int n) {
    int i = blockIdx.x * blockDim.x + threadIdx.x;
    if (i < n) g_deg[i] = 0;
}

__global__ void hist_kernel(const int* __restrict__ ew, int E) {
    int e = blockIdx.x * blockDim.x + threadIdx.x;
    if (e >= E) return;
    int d = g_is64 ? ew[4 * e + 2] : ew[2 * e + 1];
    atomicAdd(&g_deg[d], 1);
}

// Single-block exclusive scan over g_deg -> g_off (g_off[n] = E_total).
__global__ void scan_kernel(int n) {
    __shared__ int ssum[1024];
    const int t = threadIdx.x;
    const int per = (n + 1023) >> 10;
    const int s0 = t * per;
    int local = 0;
    for (int i = 0; i < per; i++) {
        int idx = s0 + i;
        if (idx < n) local += g_deg[idx];
    }
    ssum[t] = local;
    __syncthreads();
    for (int d = 1; d < 1024; d <<= 1) {
        int v = 0;
        if (t >= d) v = ssum[t - d];
        __syncthreads();
        if (t >= d) ssum[t] += v;
        __syncthreads();
    }
    int run = (t == 0) ? 0 : ssum[t - 1];
    for (int i = 0; i < per; i++) {
        int idx = s0 + i;
        if (idx < n) { g_off[idx] = run; run += g_deg[idx]; }
    }
    if (t == 1023) g_off[n] = ssum[1023];
}

__global__ void init_pos_dinv_kernel(int n) {
    int i = blockIdx.x * blockDim.x + threadIdx.x;
    if (i >= n) return;
    g_pos[i] = g_off[i];
    g_dinv[i] = rsqrtf((float)(g_deg[i] + 1));   // +1 = self-loop
}

__global__ void fill_kernel(const int* __restrict__ ew, int E) {
    int e = blockIdx.x * blockDim.x + threadIdx.x;
    if (e >= E) return;
    int s, d;
    if (g_is64) { s = ew[4 * e]; d = ew[4 * e + 2]; }
    else        { s = ew[2 * e]; d = ew[2 * e + 1]; }
    int idx = atomicAdd(&g_pos[d], 1);
    g_srcs[idx] = s;
}

// ---------------- tiled matmul: out = dinv * ([A|B] @ W), out cols = 128 ----
// Block: 256 threads, tile = 64 nodes x 128 outputs, thread tile 4x8.
template <int KA, int KB>
__global__ void mm_scale_kernel(const float* __restrict__ A,
                                const float* __restrict__ B,
                                const float* __restrict__ W,
                                float* __restrict__ out, int n) {
    constexpr int K = KA + KB;
    constexpr int KP = K + 1;
    extern __shared__ float sm[];
    float* sW  = sm;               // K * 128
    float* sIn = sm + K * HID;     // 64 * KP
    const int t  = threadIdx.x;
    const int n0 = blockIdx.x * 64;

    for (int i = t; i < K * HID; i += 256) sW[i] = W[i];
    for (int i = t; i < 64 * K; i += 256) {
        int r = i / K, c = i - r * K;
        int node = n0 + r;
        float v = 0.f;
        if (node < n) {
            if (KB == 0 || c < KA) v = A[(size_t)node * KA + c];
            else                   v = B[(size_t)node * KB + (c - KA)];
        }
        sIn[r * KP + c] = v;
    }
    __syncthreads();

    const int og = t & 15;   // 16 groups x 8 outputs
    const int ng = t >> 4;   // 16 groups x 4 nodes
    float acc[4][8];
#pragma unroll
    for (int i = 0; i < 4; i++)
#pragma unroll
        for (int j = 0; j < 8; j++) acc[i][j] = 0.f;

    const float4* sW4 = (const float4*)sW;
    const float* in0 = &sIn[(ng * 4) * KP];
#pragma unroll 4
    for (int k = 0; k < K; k++) {
        float4 w0 = sW4[k * 32 + og * 2];
        float4 w1 = sW4[k * 32 + og * 2 + 1];
        float a[4];
#pragma unroll
        for (int i = 0; i < 4; i++) a[i] = in0[i * KP + k];
#pragma unroll
        for (int i = 0; i < 4; i++) {
            acc[i][0] = fmaf(a[i], w0.x, acc[i][0]);
            acc[i][1] = fmaf(a[i], w0.y, acc[i][1]);
            acc[i][2] = fmaf(a[i], w0.z, acc[i][2]);
            acc[i][3] = fmaf(a[i], w0.w, acc[i][3]);
            acc[i][4] = fmaf(a[i], w1.x, acc[i][4]);
            acc[i][5] = fmaf(a[i], w1.y, acc[i][5]);
            acc[i][6] = fmaf(a[i], w1.z, acc[i][6]);
            acc[i][7] = fmaf(a[i], w1.w, acc[i][7]);
        }
    }

#pragma unroll
    for (int i = 0; i < 4; i++) {
        int node = n0 + ng * 4 + i;
        if (node < n) {
            float di = g_dinv[node];
            float4* o = (float4*)&out[(size_t)node * HID];
            o[og * 2]     = make_float4(acc[i][0] * di, acc[i][1] * di,
                                        acc[i][2] * di, acc[i][3] * di);
            o[og * 2 + 1] = make_float4(acc[i][4] * di, acc[i][5] * di,
                                        acc[i][6] * di, acc[i][7] * di);
        }
    }
}

// ---------------- warp-per-node gather: h[d] = relu(dinv[d]*(yw[d]+sum)+b) --
__global__ void gather_kernel(const float* __restrict__ yw,
                              const float* __restrict__ bias,
                              float* __restrict__ out, int n) {
    int gw = (blockIdx.x * blockDim.x + threadIdx.x) >> 5;
    int lane = threadIdx.x & 31;
    if (gw >= n) return;
    const float4* yw4 = (const float4*)yw;
    int beg = g_off[gw], end = g_off[gw + 1];
    float4 acc = yw4[(size_t)gw * 32 + lane];   // self-loop term
#pragma unroll 4
    for (int e = beg; e < end; e++) {
        int s = __ldg(&g_srcs[e]);
        float4 v = __ldg(&yw4[(size_t)s * 32 + lane]);
        acc.x += v.x; acc.y += v.y; acc.z += v.z; acc.w += v.w;
    }
    float di = g_dinv[gw];
    float4 b = ((const float4*)bias)[lane];
    float4 r;
    r.x = fmaxf(fmaf(di, acc.x, b.x), 0.f);
    r.y = fmaxf(fmaf(di, acc.y, b.y), 0.f);
    r.z = fmaxf(fmaf(di, acc.z, b.z), 0.f);
    r.w = fmaxf(fmaf(di, acc.w, b.w), 0.f);
    ((float4*)out)[(size_t)gw * 32 + lane] = r;
}

// ---------------- fused f4 + f5: out = sigmoid([x | relu([x|h]@W4+b4)]@w5+b5)
__global__ void f45_kernel(const float* __restrict__ X,
                           const float* __restrict__ Hin,
                           const float* __restrict__ W,
                           const float* __restrict__ b4,
                           const float* __restrict__ w5,
                           const float* __restrict__ b5,
                           float* __restrict__ out, int n) {
    constexpr int K = NFT + HID;   // 136, x first
    constexpr int KP = K + 1;
    extern __shared__ float sm[];
    float* sW    = sm;                     // 136 * 128
    float* sIn   = sm + K * HID;           // 64 * 137
    float* sPart = sIn + 64 * KP;          // 64 * 16
    const int t  = threadIdx.x;
    const int n0 = blockIdx.x * 64;

    for (int i = t; i < K * HID; i += 256) sW[i] = W[i];
    for (int i = t; i < 64 * K; i += 256) {
        int r = i / K, c = i - r * K;
        int node = n0 + r;
        float v = 0.f;
        if (node < n)
            v = (c < NFT) ? X[(size_t)node * NFT + c]
                          : Hin[(size_t)node * HID + (c - NFT)];
        sIn[r * KP + c] = v;
    }
    __syncthreads();

    const int og = t & 15, ng = t >> 4;
    float acc[4][8];
#pragma unroll
    for (int i = 0; i < 4; i++)
#pragma unroll
        for (int j = 0; j < 8; j++) acc[i][j] = 0.f;

    const float4* sW4 = (const float4*)sW;
    const float* in0 = &sIn[(ng * 4) * KP];
#pragma unroll 4
    for (int k = 0; k < K; k++) {
        float4 w0 = sW4[k * 32 + og * 2];
        float4 w1 = sW4[k * 32 + og * 2 + 1];
        float a[4];
#pragma unroll
        for (int i = 0; i < 4; i++) a[i] = in0[i * KP + k];
#pragma unroll
        for (int i = 0; i < 4; i++) {
            acc[i][0] = fmaf(a[i], w0.x, acc[i][0]);
            acc[i][1] = fmaf(a[i], w0.y, acc[i][1]);
            acc[i][2] = fmaf(a[i], w0.z, acc[i][2]);
            acc[i][3] = fmaf(a[i], w0.w, acc[i][3]);
            acc[i][4] = fmaf(a[i], w1.x, acc[i][4]);
            acc[i][5] = fmaf(a[i], w1.y, acc[i][5]);
            acc[i][6] = fmaf(a[i], w1.z, acc[i][6]);
            acc[i][7] = fmaf(a[i], w1.w, acc[i][7]);
        }
    }

    float b4l[8], w5l[8];
#pragma unroll
    for (int j = 0; j < 8; j++) {
        b4l[j] = b4[og * 8 + j];
        w5l[j] = w5[NFT + og * 8 + j];
    }
#pragma unroll
    for (int i = 0; i < 4; i++) {
        float p = 0.f;
#pragma unroll
        for (int j = 0; j < 8; j++)
            p = fmaf(fmaxf(acc[i][j] + b4l[j], 0.f), w5l[j], p);
        sPart[(ng * 4 + i) * 16 + og] = p;
    }
    __syncthreads();

    if (t < 64) {
        int node = n0 + t;
        if (node < n) {
            float s = 0.f;
#pragma unroll
            for (int o2 = 0; o2 < 16; o2++) s += sPart[t * 16 + o2];
            float xd = 0.f;
#pragma unroll
            for (int k = 0; k < NFT; k++) xd = fmaf(sIn[t * KP + k], w5[k], xd);
            float z = s + xd + b5[0];
            out[node] = 1.f / (1.f + expf(-z));
        }
    }
}

// ---------------- launch --------------------------------------------------
extern "C" void kernel_launch(void* const* d_in, const int* in_sizes, int n_in,
                              void* d_out, int out_size) {
    const float* x   = (const float*)d_in[0];
    const int*   ew  = (const int*)d_in[1];
    const float* c1W = (const float*)d_in[2];
    const float* c1b = (const float*)d_in[3];
    const float* c2W = (const float*)d_in[4];
    const float* c2b = (const float*)d_in[5];
    const float* f4W = (const float*)d_in[18];
    const float* f4b = (const float*)d_in[19];
    const float* f5W = (const float*)d_in[20];
    const float* f5b = (const float*)d_in[21];
    float* out = (float*)d_out;

    const int n = in_sizes[0] / NFT;
    long ewn = in_sizes[1];
    int E = (int)(ewn / 2);
    if (E > MAXE) E = (int)(ewn / 4);   // in case sizes count 32-bit words of int64

    float *bufA, *bufB;
    cudaGetSymbolAddress((void**)&bufA, g_bufA);
    cudaGetSymbolAddress((void**)&bufB, g_bufB);

    const int SM_MM1 = (NFT * HID + 64 * (NFT + 1)) * 4;                 // 6400 B
    const int SM_MM2 = ((HID + NFT) * HID + 64 * (HID + NFT + 1)) * 4;   // 104704 B
    const int SM_F45 = SM_MM2 + 64 * 16 * 4;                             // 108800 B
    cudaFuncSetAttribute(mm_scale_kernel<HID, NFT>,
                         cudaFuncAttributeMaxDynamicSharedMemorySize, SM_MM2);
    cudaFuncSetAttribute(f45_kernel,
                         cudaFuncAttributeMaxDynamicSharedMemorySize, SM_F45);

    const int nb256   = (n + 255) / 256;
    const int eb256   = (E + 255) / 256;
    const int mmb     = (n + 63) / 64;
    const int gatherb = ((n * 32) + 255) / 256;

    // graph build (shared by both GCN layers)
    detect_kernel<<<1, 128>>>(ew);
    zero_deg_kernel<<<nb256, 256>>>(n);
    hist_kernel<<<eb256, 256>>>(ew, E);
    scan_kernel<<<1, 1024>>>(n);
    init_pos_dinv_kernel<<<nb256, 256>>>(n);
    fill_kernel<<<eb256, 256>>>(ew, E);

    // layer 1: yw1 = dinv*(x @ c1W); h1 = relu(dinv*(self+sum)+c1b)
    mm_scale_kernel<NFT, 0><<<mmb, 256, SM_MM1>>>(x, nullptr, c1W, bufA, n);
    gather_kernel<<<gatherb, 256>>>(bufA, c1b, bufB, n);

    // layer 2: input = [h1 | x]; yw2 = dinv*([h1|x] @ c2W); h2 = relu(...)
    mm_scale_kernel<HID, NFT><<<mmb, 256, SM_MM2>>>(bufB, x, c2W, bufA, n);
    gather_kernel<<<gatherb, 256>>>(bufA, c2b, bufB, n);

    // fused f4 + f5 head: out = sigmoid([x | relu([x|h2]@f4W+f4b)] @ f5W + f5b)
    f45_kernel<<<mmb, 256, SM_F45>>>(x, bufB, f4W, f4b, f5W, f5b, out, n);
}

// round 2
// speedup vs baseline: 1.3143x; 1.3143x over previous
#include <cuda_runtime.h>
#include <cuda_fp16.h>
#include <math.h>
#include <stdint.h>

// Problem constants (fixed shapes)
#define NN   100000
#define MAXE 1600000
#define HID  128
#define NFT  8
#define KTOT 136          // HID + NFT, = 17 * 8 exactly
#define KPAD 137          // smem row stride (floats)

// ---------------- static device scratch ------------------------------------
__device__ int    g_deg[NN];
__device__ int    g_off[NN + 1];
__device__ int    g_pos[NN];
__device__ float  g_dinv[NN];
__device__ int    g_srcs[MAXE];
__device__ int    g_part[512];
__device__ __half g_yw[(size_t)NN * HID];   // fp16 messages (25.6MB)
__device__ float  g_h[(size_t)NN * HID];    // fp32 hidden  (51.2MB)
__device__ int    g_is64;

// ---------------- dtype detection: int64 vs int32 edge_index ----------------
__global__ void detect_kernel(const int* __restrict__ ew) {
    __shared__ int s_bad;
    if (threadIdx.x == 0) s_bad = 0;
    __syncthreads();
    int bad = 0;
    for (int i = threadIdx.x; i < 128; i += blockDim.x)
        if (ew[2 * i + 1] != 0) bad = 1;
    if (bad) atomicOr(&s_bad, 1);
    __syncthreads();
    if (threadIdx.x == 0) g_is64 = s_bad ? 0 : 1;
}

__global__ void hist_kernel(const int* __restrict__ ew, int E) {
    int e = blockIdx.x * blockDim.x + threadIdx.x;
    if (e >= E) return;
    int d = g_is64 ? ew[4 * e + 2] : ew[2 * e + 1];
    atomicAdd(&g_deg[d], 1);
}

// ---------------- hierarchical scan (1024 elems / 256-thread block) ---------
__device__ __forceinline__ int block_scan_excl(int v, int t, int* tot) {
    int lane = t & 31, wid = t >> 5;
    int x = v;
#pragma unroll
    for (int o = 1; o < 32; o <<= 1) {
        int y = __shfl_up_sync(0xffffffffu, x, o);
        if (lane >= o) x += y;
    }
    __shared__ int wsum[8];
    if (lane == 31) wsum[wid] = x;
    __syncthreads();
    int add = 0, total = 0;
#pragma unroll
    for (int w = 0; w < 8; w++) {
        if (w < wid) add += wsum[w];
        total += wsum[w];
    }
    *tot = total;
    __syncthreads();
    return add + x - v;   // exclusive prefix within block
}

__global__ void scan_part_kernel(int n) {
    int t = threadIdx.x, b = blockIdx.x;
    int base = b * 1024 + t * 4;
    int s = 0;
#pragma unroll
    for (int i = 0; i < 4; i++) {
        int idx = base + i;
        if (idx < n) s += g_deg[idx];
    }
    int tot;
    block_scan_excl(s, t, &tot);
    if (t == 0) g_part[b] = tot;
}

__global__ void scan_top_kernel(int nb, int n) {
    int t = threadIdx.x;
    int v = (t < nb) ? g_part[t] : 0;
    int tot;
    int e = block_scan_excl(v, t, &tot);
    if (t < nb) g_part[t] = e;
    if (t == 0) g_off[n] = tot;
}

__global__ void scan_fin_kernel(int n) {
    int t = threadIdx.x, b = blockIdx.x;
    int base = b * 1024 + t * 4;
    int d[4];
    int s = 0;
#pragma unroll
    for (int i = 0; i < 4; i++) {
        int idx = base + i;
        d[i] = (idx < n) ? g_deg[idx] : 0;
        s += d[i];
    }
    int tot;
    int e = block_scan_excl(s, t, &tot);
    int run = g_part[b] + e;
#pragma unroll
    for (int i = 0; i < 4; i++) {
        int idx = base + i;
        if (idx < n) {
            g_off[idx] = run;
            g_pos[idx] = run;
            g_dinv[idx] = rsqrtf((float)(d[i] + 1));   // +1 self-loop
            run += d[i];
        }
    }
}

__global__ void fill_kernel(const int* __restrict__ ew, int E) {
    int e = blockIdx.x * blockDim.x + threadIdx.x;
    if (e >= E) return;
    int s, d;
    if (g_is64) { s = ew[4 * e]; d = ew[4 * e + 2]; }
    else        { s = ew[2 * e]; d = ew[2 * e + 1]; }
    int idx = atomicAdd(&g_pos[d], 1);
    g_srcs[idx] = s;
}

// ---------------- layer-1 matmul (K=8, scalar), fp16 out --------------------
__global__ void mm1_kernel(const float* __restrict__ X, const float* __restrict__ W,
                           __half* __restrict__ out, int n) {
    __shared__ float sW[NFT * HID];
    __shared__ float sIn[64][NFT];
    int t = threadIdx.x, n0 = blockIdx.x * 64;
    for (int i = t; i < NFT * HID; i += 256) sW[i] = W[i];
    for (int i = t; i < 64 * NFT; i += 256) {
        int r = i >> 3, c = i & 7;
        int node = n0 + r;
        sIn[r][c] = (node < n) ? X[(size_t)node * NFT + c] : 0.f;
    }
    __syncthreads();
    int og = t & 15, ng = t >> 4;
    float acc[4][8];
#pragma unroll
    for (int i = 0; i < 4; i++)
#pragma unroll
        for (int j = 0; j < 8; j++) acc[i][j] = 0.f;
    const float4* sW4 = (const float4*)sW;
#pragma unroll
    for (int k = 0; k < NFT; k++) {
        float4 w0 = sW4[k * 32 + og * 2];
        float4 w1 = sW4[k * 32 + og * 2 + 1];
#pragma unroll
        for (int i = 0; i < 4; i++) {
            float a = sIn[ng * 4 + i][k];
            acc[i][0] = fmaf(a, w0.x, acc[i][0]);
            acc[i][1] = fmaf(a, w0.y, acc[i][1]);
            acc[i][2] = fmaf(a, w0.z, acc[i][2]);
            acc[i][3] = fmaf(a, w0.w, acc[i][3]);
            acc[i][4] = fmaf(a, w1.x, acc[i][4]);
            acc[i][5] = fmaf(a, w1.y, acc[i][5]);
            acc[i][6] = fmaf(a, w1.z, acc[i][6]);
            acc[i][7] = fmaf(a, w1.w, acc[i][7]);
        }
    }
#pragma unroll
    for (int i = 0; i < 4; i++) {
        int node = n0 + ng * 4 + i;
        if (node < n) {
            float di = g_dinv[node];
            __half2* o = (__half2*)&out[(size_t)node * HID + og * 8];
            o[0] = __floats2half2_rn(acc[i][0] * di, acc[i][1] * di);
            o[1] = __floats2half2_rn(acc[i][2] * di, acc[i][3] * di);
            o[2] = __floats2half2_rn(acc[i][4] * di, acc[i][5] * di);
            o[3] = __floats2half2_rn(acc[i][6] * di, acc[i][7] * di);
        }
    }
}

// ---------------- warp-per-node gather (fp16 msgs, fp32 accum) --------------
__global__ void gather_kernel(const __half* __restrict__ yw,
                              const float* __restrict__ bias,
                              float* __restrict__ out, int n) {
    int gw = (blockIdx.x * blockDim.x + threadIdx.x) >> 5;
    int lane = threadIdx.x & 31;
    if (gw >= n) return;
    const uint2* yw2 = (const uint2*)yw;   // 4 halves per uint2
    uint2 sv = yw2[(size_t)gw * 32 + lane];
    float2 l0 = __half22float2(*(__half2*)&sv.x);
    float2 h0 = __half22float2(*(__half2*)&sv.y);
    float4 acc = make_float4(l0.x, l0.y, h0.x, h0.y);   // self-loop term
    int beg = g_off[gw], end = g_off[gw + 1];
#pragma unroll 4
    for (int e = beg; e < end; e++) {
        int s = __ldg(&g_srcs[e]);
        uint2 v = __ldg(&yw2[(size_t)s * 32 + lane]);
        float2 l = __half22float2(*(__half2*)&v.x);
        float2 h = __half22float2(*(__half2*)&v.y);
        acc.x += l.x; acc.y += l.y; acc.z += h.x; acc.w += h.y;
    }
    float di = g_dinv[gw];
    float4 b = ((const float4*)bias)[lane];
    float4 r;
    r.x = fmaxf(fmaf(di, acc.x, b.x), 0.f);
    r.y = fmaxf(fmaf(di, acc.y, b.y), 0.f);
    r.z = fmaxf(fmaf(di, acc.z, b.z), 0.f);
    r.w = fmaxf(fmaf(di, acc.w, b.w), 0.f);
    ((float4*)out)[(size_t)gw * 32 + lane] = r;
}

// ---------------- TF32 mma machinery (m16n8k8) ------------------------------
__device__ __forceinline__ uint32_t f2tf(float x) {
    uint32_t r;
    asm("cvt.rna.tf32.f32 %0, %1;" : "=r"(r) : "f"(x));
    return r;
}

__device__ __forceinline__ void mma_tf32(float* c, const uint32_t* a, const uint32_t* b) {
    asm volatile(
        "mma.sync.aligned.m16n8k8.row.col.f32.tf32.tf32.f32 "
        "{%0,%1,%2,%3},{%4,%5,%6,%7},{%8,%9},{%0,%1,%2,%3};"
        : "+f"(c[0]), "+f"(c[1]), "+f"(c[2]), "+f"(c[3])
        : "r"(a[0]), "r"(a[1]), "r"(a[2]), "r"(a[3]), "r"(b[0]), "r"(b[1]));
}

// Assemble sIn[128][KPAD] = tf32(concat(A[KA], B[KB])) and sWt[col][k] = tf32(W^T)
template <int KA, int KB>
__device__ __forceinline__ void load_tiles(float* sIn, float* sWt,
                                           const float* __restrict__ A,
                                           const float* __restrict__ B,
                                           const float* __restrict__ W,
                                           int n0, int n, int t) {
    int warp = t >> 5, lane = t & 31;
    for (int r = warp; r < 128; r += 8) {
        int node = n0 + r;
        bool ok = node < n;
        for (int c = lane; c < KTOT; c += 32) {
            float v = 0.f;
            if (ok) v = (c < KA) ? A[(size_t)node * KA + c]
                                 : B[(size_t)node * KB + (c - KA)];
            sIn[r * KPAD + c] = __uint_as_float(f2tf(v));
        }
    }
    for (int i = t; i < KTOT * HID; i += 256) {
        int k = i >> 7, c = i & 127;           // W row-major [K][128]
        sWt[c * KPAD + k] = __uint_as_float(f2tf(W[i]));
    }
}

// Per-warp mainloop: 32 rows x 64 cols, K=136 in 17 chunks of 8.
__device__ __forceinline__ void mma_main(const float* sIn, const float* sWt,
                                         int rg, int cg, int lr, int lc,
                                         float acc[2][8][4]) {
    for (int kc = 0; kc < 17; kc++) {
        int k0 = kc * 8;
        uint32_t bfr[8][2];
#pragma unroll
        for (int g = 0; g < 8; g++) {
            int col = cg * 64 + g * 8 + lr;
            bfr[g][0] = __float_as_uint(sWt[col * KPAD + k0 + lc]);
            bfr[g][1] = __float_as_uint(sWt[col * KPAD + k0 + 4 + lc]);
        }
        uint32_t afr[2][4];
#pragma unroll
        for (int mt = 0; mt < 2; mt++) {
            int row = rg * 32 + mt * 16;
            afr[mt][0] = __float_as_uint(sIn[(row + lr) * KPAD + k0 + lc]);
            afr[mt][1] = __float_as_uint(sIn[(row + 8 + lr) * KPAD + k0 + lc]);
            afr[mt][2] = __float_as_uint(sIn[(row + lr) * KPAD + k0 + 4 + lc]);
            afr[mt][3] = __float_as_uint(sIn[(row + 8 + lr) * KPAD + k0 + 4 + lc]);
        }
#pragma unroll
        for (int mt = 0; mt < 2; mt++)
#pragma unroll
            for (int g = 0; g < 8; g++)
                mma_tf32(acc[mt][g], afr[mt], bfr[g]);
    }
}

// yw = dinv * ([A|B] @ W), fp16 out. Tile 128 rows x 128 cols, 256 threads.
template <int KA, int KB>
__global__ void __launch_bounds__(256, 1)
mm_tf32_kernel(const float* __restrict__ A, const float* __restrict__ B,
               const float* __restrict__ W, __half* __restrict__ out, int n) {
    extern __shared__ float sm[];
    float* sIn = sm;
    float* sWt = sm + 128 * KPAD;
    int t = threadIdx.x, n0 = blockIdx.x * 128;
    load_tiles<KA, KB>(sIn, sWt, A, B, W, n0, n, t);
    __syncthreads();
    int warp = t >> 5, lane = t & 31;
    int rg = warp >> 1, cg = warp & 1, lr = lane >> 2, lc = lane & 3;
    float acc[2][8][4];
#pragma unroll
    for (int mt = 0; mt < 2; mt++)
#pragma unroll
        for (int g = 0; g < 8; g++)
#pragma unroll
            for (int j = 0; j < 4; j++) acc[mt][g][j] = 0.f;
    mma_main(sIn, sWt, rg, cg, lr, lc, acc);
#pragma unroll
    for (int mt = 0; mt < 2; mt++) {
        int r0 = n0 + rg * 32 + mt * 16 + lr;
        int r1 = r0 + 8;
        float d0 = (r0 < n) ? g_dinv[r0] : 0.f;
        float d1 = (r1 < n) ? g_dinv[r1] : 0.f;
#pragma unroll
        for (int g = 0; g < 8; g++) {
            int col = cg * 64 + g * 8 + 2 * lc;
            if (r0 < n)
                *(__half2*)&out[(size_t)r0 * HID + col] =
                    __floats2half2_rn(acc[mt][g][0] * d0, acc[mt][g][1] * d0);
            if (r1 < n)
                *(__half2*)&out[(size_t)r1 * HID + col] =
                    __floats2half2_rn(acc[mt][g][2] * d1, acc[mt][g][3] * d1);
        }
    }
}

// fused f4+f5: out = sigmoid([x | relu([x|h]@W4+b4)] @ w5 + b5)
__global__ void __launch_bounds__(256, 1)
f45_tf32_kernel(const float* __restrict__ X, const float* __restrict__ Hin,
                const float* __restrict__ W, const float* __restrict__ b4,
                const float* __restrict__ w5, const float* __restrict__ b5,
                float* __restrict__ out, int n) {
    extern __shared__ float sm[];
    float* sIn = sm;
    float* sWt = sm + 128 * KPAD;
    float* sPart = sWt + 128 * KPAD;     // [128][2]
    int t = threadIdx.x, n0 = blockIdx.x * 128;
    load_tiles<NFT, HID>(sIn, sWt, X, Hin, W, n0, n, t);
    __syncthreads();
    int warp = t >> 5, lane = t & 31;
    int rg = warp >> 1, cg = warp & 1, lr = lane >> 2, lc = lane & 3;
    float acc[2][8][4];
#pragma unroll
    for (int mt = 0; mt < 2; mt++)
#pragma unroll
        for (int g = 0; g < 8; g++)
#pragma unroll
            for (int j = 0; j < 4; j++) acc[mt][g][j] = 0.f;
    mma_main(sIn, sWt, rg, cg, lr, lc, acc);

    float b4l[8][2], w5l[8][2];
#pragma unroll
    for (int g = 0; g < 8; g++) {
        int col = cg * 64 + g * 8 + 2 * lc;
        b4l[g][0] = b4[col];         b4l[g][1] = b4[col + 1];
        w5l[g][0] = w5[NFT + col];   w5l[g][1] = w5[NFT + col + 1];
    }
#pragma unroll
    for (int mt = 0; mt < 2; mt++)
#pragma unroll
        for (int h = 0; h < 2; h++) {
            float p = 0.f;
#pragma unroll
            for (int g = 0; g < 8; g++) {
                p = fmaf(fmaxf(acc[mt][g][2 * h] + b4l[g][0], 0.f), w5l[g][0], p);
                p = fmaf(fmaxf(acc[mt][g][2 * h + 1] + b4l[g][1], 0.f), w5l[g][1], p);
            }
            p += __shfl_xor_sync(0xffffffffu, p, 1);
            p += __shfl_xor_sync(0xffffffffu, p, 2);
            if (lc == 0) {
                int rl = rg * 32 + mt * 16 + h * 8 + lr;
                sPart[rl * 2 + cg] = p;
            }
        }
    __syncthreads();
    if (t < 128) {
        int node = n0 + t;
        if (node < n) {
            float s = sPart[t * 2] + sPart[t * 2 + 1] + b5[0];
#pragma unroll
            for (int k = 0; k < NFT; k++) s = fmaf(sIn[t * KPAD + k], w5[k], s);
            out[node] = 1.f / (1.f + expf(-s));
        }
    }
}

// ---------------- launch ----------------------------------------------------
extern "C" void kernel_launch(void* const* d_in, const int* in_sizes, int n_in,
                              void* d_out, int out_size) {
    const float* x   = (const float*)d_in[0];
    const int*   ew  = (const int*)d_in[1];
    const float* c1W = (const float*)d_in[2];
    const float* c1b = (const float*)d_in[3];
    const float* c2W = (const float*)d_in[4];
    const float* c2b = (const float*)d_in[5];
    const float* f4W = (const float*)d_in[18];
    const float* f4b = (const float*)d_in[19];
    const float* f5W = (const float*)d_in[20];
    const float* f5b = (const float*)d_in[21];
    float* out = (float*)d_out;

    const int n = in_sizes[0] / NFT;
    long ewn = in_sizes[1];
    int E = (int)(ewn / 2);
    if (E > MAXE) E = (int)(ewn / 4);

    __half* yw; float* h; int* degp;
    cudaGetSymbolAddress((void**)&yw, g_yw);
    cudaGetSymbolAddress((void**)&h, g_h);
    cudaGetSymbolAddress((void**)&degp, g_deg);

    const int SM_MM  = 2 * 128 * KPAD * 4;              // 140288 B
    const int SM_F45 = SM_MM + 128 * 2 * 4;             // 141312 B
    cudaFuncSetAttribute(mm_tf32_kernel<HID, NFT>,
                         cudaFuncAttributeMaxDynamicSharedMemorySize, SM_MM);
    cudaFuncSetAttribute(f45_tf32_kernel,
                         cudaFuncAttributeMaxDynamicSharedMemorySize, SM_F45);

    const int eb256   = (E + 255) / 256;
    const int nb1024  = (n + 1023) / 1024;
    const int mm1b    = (n + 63) / 64;
    const int mmb     = (n + 127) / 128;
    const int gatherb = ((n * 32) + 255) / 256;

    // graph build (shared by both GCN layers)
    detect_kernel<<<1, 128>>>(ew);
    cudaMemsetAsync(degp, 0, (size_t)n * sizeof(int), 0);
    hist_kernel<<<eb256, 256>>>(ew, E);
    scan_part_kernel<<<nb1024, 256>>>(n);
    scan_top_kernel<<<1, 256>>>(nb1024, n);
    scan_fin_kernel<<<nb1024, 256>>>(n);
    fill_kernel<<<eb256, 256>>>(ew, E);

    // layer 1: yw1 = dinv*(x @ c1W) [fp16]; h1 = relu(dinv*(self+sum)+c1b)
    mm1_kernel<<<mm1b, 256>>>(x, c1W, yw, n);
    gather_kernel<<<gatherb, 256>>>(yw, c1b, h, n);

    // layer 2: yw2 = dinv*([h1|x] @ c2W) [tf32 mma, fp16 out]; h2 = relu(...)
    mm_tf32_kernel<HID, NFT><<<mmb, 256, SM_MM>>>(h, x, c2W, yw, n);
    gather_kernel<<<gatherb, 256>>>(yw, c2b, h, n);

    // fused head: out = sigmoid([x | relu([x|h2]@f4W+f4b)] @ f5W + f5b)
    f45_tf32_kernel<<<mmb, 256, SM_F45>>>(x, h, f4W, f4b, f5W, f5b, out, n);
}

// round 3
// speedup vs baseline: 2.1455x; 1.6325x over previous
#include <cuda_runtime.h>
#include <cuda_fp16.h>
#include <math.h>
#include <stdint.h>

// Problem constants (fixed shapes)
#define NN   100000
#define MAXE 1600000
#define HID  128
#define NFT  8
#define KTOT 136          // HID + NFT = 17 * 8
#define KPAD 137          // smem row stride (floats)

// ---------------- static device scratch ------------------------------------
__device__ int    g_deg[NN];
__device__ int    g_off[NN + 1];
__device__ int    g_pos[NN];
__device__ float  g_dinv[NN];
__device__ int    g_srcs[MAXE];
__device__ int    g_part[512];
__device__ __half g_yw[(size_t)NN * HID];   // fp16 messages (25.6MB)
__device__ __half g_h[(size_t)NN * HID];    // fp16 hidden   (25.6MB)
__device__ int    g_is64;

// ---------------- dtype detection: int64 vs int32 edge_index ----------------
__global__ void detect_kernel(const int* __restrict__ ew) {
    __shared__ int s_bad;
    if (threadIdx.x == 0) s_bad = 0;
    __syncthreads();
    int bad = 0;
    for (int i = threadIdx.x; i < 128; i += blockDim.x)
        if (ew[2 * i + 1] != 0) bad = 1;
    if (bad) atomicOr(&s_bad, 1);
    __syncthreads();
    if (threadIdx.x == 0) g_is64 = s_bad ? 0 : 1;
}

__global__ void hist_kernel(const int* __restrict__ ew, int E) {
    int e = blockIdx.x * blockDim.x + threadIdx.x;
    if (e >= E) return;
    int d;
    if (g_is64) { int4 v = ((const int4*)ew)[e]; d = v.z; }
    else        { int2 v = ((const int2*)ew)[e]; d = v.y; }
    atomicAdd(&g_deg[d], 1);
}

// ---------------- hierarchical scan (1024 elems / 256-thread block) ---------
__device__ __forceinline__ int block_scan_excl(int v, int t, int* tot) {
    int lane = t & 31, wid = t >> 5;
    int x = v;
#pragma unroll
    for (int o = 1; o < 32; o <<= 1) {
        int y = __shfl_up_sync(0xffffffffu, x, o);
        if (lane >= o) x += y;
    }
    __shared__ int wsum[8];
    if (lane == 31) wsum[wid] = x;
    __syncthreads();
    int add = 0, total = 0;
#pragma unroll
    for (int w = 0; w < 8; w++) {
        if (w < wid) add += wsum[w];
        total += wsum[w];
    }
    *tot = total;
    __syncthreads();
    return add + x - v;
}

__global__ void scan_part_kernel(int n) {
    int t = threadIdx.x, b = blockIdx.x;
    int base = b * 1024 + t * 4;
    int s = 0;
#pragma unroll
    for (int i = 0; i < 4; i++) {
        int idx = base + i;
        if (idx < n) s += g_deg[idx];
    }
    int tot;
    block_scan_excl(s, t, &tot);
    if (t == 0) g_part[b] = tot;
}

__global__ void scan_top_kernel(int nb, int n) {
    int t = threadIdx.x;
    int v = (t < nb) ? g_part[t] : 0;
    int tot;
    int e = block_scan_excl(v, t, &tot);
    if (t < nb) g_part[t] = e;
    if (t == 0) g_off[n] = tot;
}

__global__ void scan_fin_kernel(int n) {
    int t = threadIdx.x, b = blockIdx.x;
    int base = b * 1024 + t * 4;
    int d[4];
    int s = 0;
#pragma unroll
    for (int i = 0; i < 4; i++) {
        int idx = base + i;
        d[i] = (idx < n) ? g_deg[idx] : 0;
        s += d[i];
    }
    int tot;
    int e = block_scan_excl(s, t, &tot);
    int run = g_part[b] + e;
#pragma unroll
    for (int i = 0; i < 4; i++) {
        int idx = base + i;
        if (idx < n) {
            g_off[idx] = run;
            g_pos[idx] = run;
            g_dinv[idx] = rsqrtf((float)(d[i] + 1));   // +1 self-loop
            run += d[i];
        }
    }
}

__global__ void fill_kernel(const int* __restrict__ ew, int E) {
    int e = blockIdx.x * blockDim.x + threadIdx.x;
    if (e >= E) return;
    int s, d;
    if (g_is64) { int4 v = ((const int4*)ew)[e]; s = v.x; d = v.z; }
    else        { int2 v = ((const int2*)ew)[e]; s = v.x; d = v.y; }
    int idx = atomicAdd(&g_pos[d], 1);
    g_srcs[idx] = s;
}

// ---------------- layer-1 matmul (K=8, scalar), fp16 out --------------------
__global__ void mm1_kernel(const float* __restrict__ X, const float* __restrict__ W,
                           __half* __restrict__ out, int n) {
    __shared__ float sW[NFT * HID];
    __shared__ float sIn[64][NFT];
    int t = threadIdx.x, n0 = blockIdx.x * 64;
    for (int i = t; i < NFT * HID; i += 256) sW[i] = W[i];
    for (int i = t; i < 64 * NFT; i += 256) {
        int r = i >> 3, c = i & 7;
        int node = n0 + r;
        sIn[r][c] = (node < n) ? X[(size_t)node * NFT + c] : 0.f;
    }
    __syncthreads();
    int og = t & 15, ng = t >> 4;
    float acc[4][8];
#pragma unroll
    for (int i = 0; i < 4; i++)
#pragma unroll
        for (int j = 0; j < 8; j++) acc[i][j] = 0.f;
    const float4* sW4 = (const float4*)sW;
#pragma unroll
    for (int k = 0; k < NFT; k++) {
        float4 w0 = sW4[k * 32 + og * 2];
        float4 w1 = sW4[k * 32 + og * 2 + 1];
#pragma unroll
        for (int i = 0; i < 4; i++) {
            float a = sIn[ng * 4 + i][k];
            acc[i][0] = fmaf(a, w0.x, acc[i][0]);
            acc[i][1] = fmaf(a, w0.y, acc[i][1]);
            acc[i][2] = fmaf(a, w0.z, acc[i][2]);
            acc[i][3] = fmaf(a, w0.w, acc[i][3]);
            acc[i][4] = fmaf(a, w1.x, acc[i][4]);
            acc[i][5] = fmaf(a, w1.y, acc[i][5]);
            acc[i][6] = fmaf(a, w1.z, acc[i][6]);
            acc[i][7] = fmaf(a, w1.w, acc[i][7]);
        }
    }
#pragma unroll
    for (int i = 0; i < 4; i++) {
        int node = n0 + ng * 4 + i;
        if (node < n) {
            float di = g_dinv[node];
            __half2* o = (__half2*)&out[(size_t)node * HID + og * 8];
            o[0] = __floats2half2_rn(acc[i][0] * di, acc[i][1] * di);
            o[1] = __floats2half2_rn(acc[i][2] * di, acc[i][3] * di);
            o[2] = __floats2half2_rn(acc[i][4] * di, acc[i][5] * di);
            o[3] = __floats2half2_rn(acc[i][6] * di, acc[i][7] * di);
        }
    }
}

// ---------------- gather: warp/node, 2 edges per iteration ------------------
// h[d] = relu(dinv[d]*(yw[d] + sum_{s in N(d)} yw[s]) + b), fp16 in, fp16 out.
__global__ void gather_kernel(const __half* __restrict__ yw,
                              const float* __restrict__ bias,
                              __half* __restrict__ out, int n) {
    int gw = (blockIdx.x * blockDim.x + threadIdx.x) >> 5;
    if (gw >= n) return;                    // uniform per warp
    int lane = threadIdx.x & 31;
    int hh = lane >> 4;                     // which edge of the pair
    int fl = lane & 15;                     // 16B feature chunk (8 halves)
    const uint4* yw4 = (const uint4*)yw;    // 16 uint4 per 128-half row

    float acc[8];
#pragma unroll
    for (int j = 0; j < 8; j++) acc[j] = 0.f;

    // self-loop term (counted once, by half 0)
    if (hh == 0) {
        uint4 v = yw4[(size_t)gw * 16 + fl];
        float2 a = __half22float2(*(__half2*)&v.x);
        float2 b = __half22float2(*(__half2*)&v.y);
        float2 c = __half22float2(*(__half2*)&v.z);
        float2 d = __half22float2(*(__half2*)&v.w);
        acc[0] = a.x; acc[1] = a.y; acc[2] = b.x; acc[3] = b.y;
        acc[4] = c.x; acc[5] = c.y; acc[6] = d.x; acc[7] = d.y;
    }

    int beg = g_off[gw], end = g_off[gw + 1];
    for (int base = beg; base < end; base += 32) {
        int idx = base + lane;
        int sreg = (idx < end) ? g_srcs[idx] : 0;
        int m = min(32, end - base);
#pragma unroll 4
        for (int i2 = 0; i2 < m; i2 += 2) {
            int e = i2 + hh;                              // e <= 31 always
            int s = __shfl_sync(0xffffffffu, sreg, e);
            if (e < m) {
                uint4 v = __ldg(&yw4[(size_t)s * 16 + fl]);
                float2 a = __half22float2(*(__half2*)&v.x);
                float2 b = __half22float2(*(__half2*)&v.y);
                float2 c = __half22float2(*(__half2*)&v.z);
                float2 d = __half22float2(*(__half2*)&v.w);
                acc[0] += a.x; acc[1] += a.y; acc[2] += b.x; acc[3] += b.y;
                acc[4] += c.x; acc[5] += c.y; acc[6] += d.x; acc[7] += d.y;
            }
        }
    }

    // combine the two edge-halves (lane l <-> l+16 hold same features)
#pragma unroll
    for (int j = 0; j < 8; j++)
        acc[j] += __shfl_xor_sync(0xffffffffu, acc[j], 16);

    if (hh == 0) {
        float di = g_dinv[gw];
        const float4* b4 = (const float4*)bias;
        float4 ba = b4[fl * 2], bb = b4[fl * 2 + 1];
        float r0 = fmaxf(fmaf(di, acc[0], ba.x), 0.f);
        float r1 = fmaxf(fmaf(di, acc[1], ba.y), 0.f);
        float r2 = fmaxf(fmaf(di, acc[2], ba.z), 0.f);
        float r3 = fmaxf(fmaf(di, acc[3], ba.w), 0.f);
        float r4 = fmaxf(fmaf(di, acc[4], bb.x), 0.f);
        float r5 = fmaxf(fmaf(di, acc[5], bb.y), 0.f);
        float r6 = fmaxf(fmaf(di, acc[6], bb.z), 0.f);
        float r7 = fmaxf(fmaf(di, acc[7], bb.w), 0.f);
        uint4 o;
        *(__half2*)&o.x = __floats2half2_rn(r0, r1);
        *(__half2*)&o.y = __floats2half2_rn(r2, r3);
        *(__half2*)&o.z = __floats2half2_rn(r4, r5);
        *(__half2*)&o.w = __floats2half2_rn(r6, r7);
        ((uint4*)out)[(size_t)gw * 16 + fl] = o;
    }
}

// ---------------- TF32 mma machinery (m16n8k8) ------------------------------
__device__ __forceinline__ uint32_t f2tf(float x) {
    uint32_t r;
    asm("cvt.rna.tf32.f32 %0, %1;" : "=r"(r) : "f"(x));
    return r;
}

__device__ __forceinline__ void mma_tf32(float* c, const uint32_t* a, const uint32_t* b) {
    asm volatile(
        "mma.sync.aligned.m16n8k8.row.col.f32.tf32.tf32.f32 "
        "{%0,%1,%2,%3},{%4,%5,%6,%7},{%8,%9},{%0,%1,%2,%3};"
        : "+f"(c[0]), "+f"(c[1]), "+f"(c[2]), "+f"(c[3])
        : "r"(a[0]), "r"(a[1]), "r"(a[2]), "r"(a[3]), "r"(b[0]), "r"(b[1]));
}

// sIn[256][KPAD] = tf32(concat), sWt[col][k] = tf32(W^T). 512 threads.
// XFIRST: input = [X(8) | H(128)]; else [H(128) | X(8)].
template <bool XFIRST>
__device__ __forceinline__ void load_tiles(float* sIn, float* sWt,
                                           const float* __restrict__ X,
                                           const __half* __restrict__ H,
                                           const float* __restrict__ W,
                                           int n0, int n, int t) {
    int warp = t >> 5, lane = t & 31;
    for (int r = warp; r < 256; r += 16) {
        int node = n0 + r;
        bool ok = node < n;
        for (int c = lane; c < KTOT; c += 32) {
            float v = 0.f;
            if (ok) {
                if (XFIRST) v = (c < NFT) ? X[(size_t)node * NFT + c]
                                          : __half2float(H[(size_t)node * HID + (c - NFT)]);
                else        v = (c < HID) ? __half2float(H[(size_t)node * HID + c])
                                          : X[(size_t)node * NFT + (c - HID)];
            }
            sIn[r * KPAD + c] = __uint_as_float(f2tf(v));
        }
    }
    for (int i = t; i < KTOT * HID; i += 512) {
        int k = i >> 7, c = i & 127;           // W row-major [K][128]
        sWt[c * KPAD + k] = __uint_as_float(f2tf(W[i]));
    }
}

// Per-warp mainloop: 32 rows x 64 cols, K=136 in 17 chunks of 8.
__device__ __forceinline__ void mma_main(const float* sIn, const float* sWt,
                                         int rg, int cg, int lr, int lc,
                                         float acc[2][8][4]) {
    for (int kc = 0; kc < 17; kc++) {
        int k0 = kc * 8;
        uint32_t bfr[8][2];
#pragma unroll
        for (int g = 0; g < 8; g++) {
            int col = cg * 64 + g * 8 + lr;
            bfr[g][0] = __float_as_uint(sWt[col * KPAD + k0 + lc]);
            bfr[g][1] = __float_as_uint(sWt[col * KPAD + k0 + 4 + lc]);
        }
        uint32_t afr[2][4];
#pragma unroll
        for (int mt = 0; mt < 2; mt++) {
            int row = rg * 32 + mt * 16;
            afr[mt][0] = __float_as_uint(sIn[(row + lr) * KPAD + k0 + lc]);
            afr[mt][1] = __float_as_uint(sIn[(row + 8 + lr) * KPAD + k0 + lc]);
            afr[mt][2] = __float_as_uint(sIn[(row + lr) * KPAD + k0 + 4 + lc]);
            afr[mt][3] = __float_as_uint(sIn[(row + 8 + lr) * KPAD + k0 + 4 + lc]);
        }
#pragma unroll
        for (int mt = 0; mt < 2; mt++)
#pragma unroll
            for (int g = 0; g < 8; g++)
                mma_tf32(acc[mt][g], afr[mt], bfr[g]);
    }
}

// yw = dinv * ([H|X] @ W), fp16 out. Tile 256 rows x 128 cols, 512 threads.
__global__ void __launch_bounds__(512, 1)
mm2_tf32_kernel(const float* __restrict__ X, const __half* __restrict__ H,
                const float* __restrict__ W, __half* __restrict__ out, int n) {
    extern __shared__ float sm[];
    float* sIn = sm;
    float* sWt = sm + 256 * KPAD;
    int t = threadIdx.x, n0 = blockIdx.x * 256;
    load_tiles<false>(sIn, sWt, X, H, W, n0, n, t);
    __syncthreads();
    int warp = t >> 5, lane = t & 31;
    int rg = warp >> 1, cg = warp & 1, lr = lane >> 2, lc = lane & 3;
    float acc[2][8][4];
#pragma unroll
    for (int mt = 0; mt < 2; mt++)
#pragma unroll
        for (int g = 0; g < 8; g++)
#pragma unroll
            for (int j = 0; j < 4; j++) acc[mt][g][j] = 0.f;
    mma_main(sIn, sWt, rg, cg, lr, lc, acc);
#pragma unroll
    for (int mt = 0; mt < 2; mt++) {
        int r0 = n0 + rg * 32 + mt * 16 + lr;
        int r1 = r0 + 8;
        float d0 = (r0 < n) ? g_dinv[r0] : 0.f;
        float d1 = (r1 < n) ? g_dinv[r1] : 0.f;
#pragma unroll
        for (int g = 0; g < 8; g++) {
            int col = cg * 64 + g * 8 + 2 * lc;
            if (r0 < n)
                *(__half2*)&out[(size_t)r0 * HID + col] =
                    __floats2half2_rn(acc[mt][g][0] * d0, acc[mt][g][1] * d0);
            if (r1 < n)
                *(__half2*)&out[(size_t)r1 * HID + col] =
                    __floats2half2_rn(acc[mt][g][2] * d1, acc[mt][g][3] * d1);
        }
    }
}

// fused f4+f5: out = sigmoid([x | relu([x|h]@W4+b4)] @ w5 + b5)
__global__ void __launch_bounds__(512, 1)
f45_tf32_kernel(const float* __restrict__ X, const __half* __restrict__ Hin,
                const float* __restrict__ W, const float* __restrict__ b4,
                const float* __restrict__ w5, const float* __restrict__ b5,
                float* __restrict__ out, int n) {
    extern __shared__ float sm[];
    float* sIn = sm;
    float* sWt = sm + 256 * KPAD;
    float* sPart = sWt + 128 * KPAD;     // after sWt: [256][2]
    int t = threadIdx.x, n0 = blockIdx.x * 256;
    load_tiles<true>(sIn, sWt, X, Hin, W, n0, n, t);
    __syncthreads();
    int warp = t >> 5, lane = t & 31;
    int rg = warp >> 1, cg = warp & 1, lr = lane >> 2, lc = lane & 3;
    float acc[2][8][4];
#pragma unroll
    for (int mt = 0; mt < 2; mt++)
#pragma unroll
        for (int g = 0; g < 8; g++)
#pragma unroll
            for (int j = 0; j < 4; j++) acc[mt][g][j] = 0.f;
    mma_main(sIn, sWt, rg, cg, lr, lc, acc);

    float b4l[8][2], w5l[8][2];
#pragma unroll
    for (int g = 0; g < 8; g++) {
        int col = cg * 64 + g * 8 + 2 * lc;
        b4l[g][0] = b4[col];         b4l[g][1] = b4[col + 1];
        w5l[g][0] = w5[NFT + col];   w5l[g][1] = w5[NFT + col + 1];
    }
#pragma unroll
    for (int mt = 0; mt < 2; mt++)
#pragma unroll
        for (int h = 0; h < 2; h++) {
            float p = 0.f;
#pragma unroll
            for (int g = 0; g < 8; g++) {
                p = fmaf(fmaxf(acc[mt][g][2 * h] + b4l[g][0], 0.f), w5l[g][0], p);
                p = fmaf(fmaxf(acc[mt][g][2 * h + 1] + b4l[g][1], 0.f), w5l[g][1], p);
            }
            p += __shfl_xor_sync(0xffffffffu, p, 1);
            p += __shfl_xor_sync(0xffffffffu, p, 2);
            if (lc == 0) {
                int rl = rg * 32 + mt * 16 + h * 8 + lr;
                sPart[rl * 2 + cg] = p;
            }
        }
    __syncthreads();
    if (t < 256) {
        int node = n0 + t;
        if (node < n) {
            float s = sPart[t * 2] + sPart[t * 2 + 1] + b5[0];
#pragma unroll
            for (int k = 0; k < NFT; k++) s = fmaf(sIn[t * KPAD + k], w5[k], s);
            out[node] = 1.f / (1.f + expf(-s));
        }
    }
}

// ---------------- launch ----------------------------------------------------
extern "C" void kernel_launch(void* const* d_in, const int* in_sizes, int n_in,
                              void* d_out, int out_size) {
    const float* x   = (const float*)d_in[0];
    const int*   ew  = (const int*)d_in[1];
    const float* c1W = (const float*)d_in[2];
    const float* c1b = (const float*)d_in[3];
    const float* c2W = (const float*)d_in[4];
    const float* c2b = (const float*)d_in[5];
    const float* f4W = (const float*)d_in[18];
    const float* f4b = (const float*)d_in[19];
    const float* f5W = (const float*)d_in[20];
    const float* f5b = (const float*)d_in[21];
    float* out = (float*)d_out;

    const int n = in_sizes[0] / NFT;
    long ewn = in_sizes[1];
    int E = (int)(ewn / 2);
    if (E > MAXE) E = (int)(ewn / 4);

    __half* yw; __half* h; int* degp;
    cudaGetSymbolAddress((void**)&yw, g_yw);
    cudaGetSymbolAddress((void**)&h, g_h);
    cudaGetSymbolAddress((void**)&degp, g_deg);

    const int SM_MM  = (256 * KPAD + 128 * KPAD) * 4;        // 210432 B
    const int SM_F45 = SM_MM + 256 * 2 * 4;                  // 212480 B
    cudaFuncSetAttribute(mm2_tf32_kernel,
                         cudaFuncAttributeMaxDynamicSharedMemorySize, SM_MM);
    cudaFuncSetAttribute(f45_tf32_kernel,
                         cudaFuncAttributeMaxDynamicSharedMemorySize, SM_F45);

    const int eb256   = (E + 255) / 256;
    const int nb1024  = (n + 1023) / 1024;
    const int mm1b    = (n + 63) / 64;
    const int mmb     = (n + 255) / 256;
    const int gatherb = (n + 7) / 8;     // 8 warps (nodes) per 256-thread block

    // graph build (shared by both GCN layers)
    detect_kernel<<<1, 128>>>(ew);
    cudaMemsetAsync(degp, 0, (size_t)n * sizeof(int), 0);
    hist_kernel<<<eb256, 256>>>(ew, E);
    scan_part_kernel<<<nb1024, 256>>>(n);
    scan_top_kernel<<<1, 256>>>(nb1024, n);
    scan_fin_kernel<<<nb1024, 256>>>(n);
    fill_kernel<<<eb256, 256>>>(ew, E);

    // layer 1: yw1 = dinv*(x @ c1W) [fp16]; h1 = relu(dinv*(self+sum)+c1b)
    mm1_kernel<<<mm1b, 256>>>(x, c1W, yw, n);
    gather_kernel<<<gatherb, 256>>>(yw, c1b, h, n);

    // layer 2: yw2 = dinv*([h1|x] @ c2W) [tf32 mma]; h2 = relu(...)
    mm2_tf32_kernel<<<mmb, 512, SM_MM>>>(x, h, c2W, yw, n);
    gather_kernel<<<gatherb, 256>>>(yw, c2b, h, n);

    // fused head: out = sigmoid([x | relu([x|h2]@f4W+f4b)] @ f5W + f5b)
    f45_tf32_kernel<<<mmb, 512, SM_F45>>>(x, h, f4W, f4b, f5W, f5b, out, n);
}